// round 16
// baseline (speedup 1.0000x reference)
#include <cuda_runtime.h>
#include <cuda_fp16.h>
#include <cstdint>
#include <cstddef>

// Problem dims (fixed by the dataset)
#define T_TOK 8192
#define KDIM  4096
#define ODIM  4096

// GEMM tiling
#define BM 128
#define BN 128
#define BK 64                 // 64 fp16 = 128 B per smem row (full SW128)
#define STAGES 3
#define KTILES (KDIM / BK)    // 64

#define A_ST_BYTES (BM * 128) // 16384
#define B_ST_BYTES (BN * 128) // 16384
#define STAGE_BYTES (A_ST_BYTES + B_ST_BYTES)   // 32768
#define SMEM_TOTAL (1024 + STAGES * STAGE_BYTES) // 99328 (2 CTAs fit in 228K)

// fp16 scratch for converted operands (allocation-free: device globals)
__device__ __half g_A[(size_t)T_TOK * KDIM];   // 64 MB
__device__ __half g_B[(size_t)ODIM * KDIM];    // 32 MB

// ---------------- helpers ----------------
__device__ __forceinline__ uint32_t smem_u32(const void* p) {
    uint32_t a;
    asm("{ .reg .u64 t; cvta.to.shared.u64 t, %1; cvt.u32.u64 %0, t; }"
        : "=r"(a) : "l"(p));
    return a;
}

__device__ __forceinline__ uint32_t h2_bits(__half2 h) {
    uint32_t u;
    *reinterpret_cast<__half2*>(&u) = h;
    return u;
}

// SW128 swizzle for 128B rows: XOR 16B-chunk bits [6:4] with row bits [9:7]
__device__ __forceinline__ uint32_t swz(uint32_t off) {
    return off ^ ((off >> 3) & 0x70);
}

#define CP16(dst, src) \
    asm volatile("cp.async.cg.shared.global [%0], [%1], 16;" \
                 :: "r"(dst), "l"(src) : "memory")

// one arrival on [mbar] when ALL of this thread's prior cp.asyncs complete
#define CP_MB_ARRIVE(mbar) \
    asm volatile("cp.async.mbarrier.arrive.noinc.shared::cta.b64 [%0];" \
                 :: "r"(mbar) : "memory")

#define MB_INIT(a, c) \
    asm volatile("mbarrier.init.shared.b64 [%0], %1;" :: "r"(a), "r"(c) : "memory")

#define MB_WAIT(addr, ph) do {                                                     \
    uint32_t _done = 0;                                                            \
    while (!_done) {                                                               \
        asm volatile("{\n\t.reg .pred p;\n\t"                                      \
            "mbarrier.try_wait.parity.acquire.cta.shared::cta.b64 p, [%1], %2, 0x989680;\n\t" \
            "selp.b32 %0, 1, 0, p;\n\t}"                                           \
            : "=r"(_done) : "r"((uint32_t)(addr)), "r"((uint32_t)(ph)) : "memory"); \
    }                                                                              \
} while (0)

#define LDSM4(r, a)                                                             \
    asm volatile("ldmatrix.sync.aligned.m8n8.x4.shared.b16 {%0,%1,%2,%3}, [%4];" \
        : "=r"((r)[0]), "=r"((r)[1]), "=r"((r)[2]), "=r"((r)[3]) : "r"(a))

__device__ __forceinline__ void mma16816(float* d, const uint32_t* a,
                                         const uint32_t* b) {
    asm volatile(
        "mma.sync.aligned.m16n8k16.row.col.f32.f16.f16.f32 "
        "{%0,%1,%2,%3}, {%4,%5,%6,%7}, {%8,%9}, {%0,%1,%2,%3};"
        : "+f"(d[0]), "+f"(d[1]), "+f"(d[2]), "+f"(d[3])
        : "r"(a[0]), "r"(a[1]), "r"(a[2]), "r"(a[3]), "r"(b[0]), "r"(b[1]));
}

// ---------------- fused convert fp32 -> fp16 (lossless: exact ints <= 448) ----
__global__ void cvt_fused_kernel(const float* __restrict__ qx,
                                 const float* __restrict__ W,
                                 __half* __restrict__ dA, __half* __restrict__ dB,
                                 size_t nA8, size_t nTot8) {
    size_t i = (size_t)blockIdx.x * blockDim.x + threadIdx.x;
    size_t stride = (size_t)gridDim.x * blockDim.x;
    for (; i < nTot8; i += stride) {
        const float4* s4;
        uint4* d4;
        if (i < nA8) {
            s4 = (const float4*)qx + 2 * i;
            d4 = (uint4*)dA + i;
        } else {
            size_t j = i - nA8;
            s4 = (const float4*)W + 2 * j;
            d4 = (uint4*)dB + j;
        }
        float4 v0 = s4[0];
        float4 v1 = s4[1];
        uint4 o;
        o.x = h2_bits(__floats2half2_rn(v0.x, v0.y));
        o.y = h2_bits(__floats2half2_rn(v0.z, v0.w));
        o.z = h2_bits(__floats2half2_rn(v1.x, v1.y));
        o.w = h2_bits(__floats2half2_rn(v1.z, v1.w));
        *d4 = o;
    }
}

// ---------------- pipelined HMMA GEMM + fused dequant epilogue ----------------
// One sync event per direction per iteration:
//   producer->consumer: full[s] mbarrier (256 cp.async arrivals)
//   consumer->producer: end-of-iteration __syncthreads — with 3 stages, the
//   fill target at iter kt is exactly the stage consumed at iter kt-1, so the
//   barrier at the end of kt-1 already proves it free.  No empty barriers.
__global__ void __launch_bounds__(256, 2)
qgemm_kernel(const float* __restrict__ scale_x, const float* __restrict__ scale_w,
             const float* __restrict__ gscale,  const float* __restrict__ bias,
             float* __restrict__ out) {
    extern __shared__ char smem[];
    uint32_t sb = smem_u32(smem);
    int tid = threadIdx.x;
    int lane = tid & 31;
    int wid = tid >> 5;          // 0..7
    int wm = wid >> 1;           // 0..3   (M dim, 32 rows each)
    int wn = wid & 1;            // 0..1   (N dim, 64 cols each)
    int m0 = blockIdx.y * BM;
    int n0 = blockIdx.x * BN;

    // mbarriers: full[s] at sb+8s; stages at sb+1024
    if (tid == 0) {
        #pragma unroll
        for (int s3 = 0; s3 < STAGES; s3++)
            MB_INIT(sb + 8 * s3, 256);
    }
    __syncthreads();
    uint32_t stg = sb + 1024;

    // ---- cp.async thread mapping: 8 x 16B chunks per thread per stage ----
    int r0c = tid >> 3, cc = tid & 7;    // base row 0..31 / chunk col

    const char* Ag = (const char*)(g_A + (size_t)(m0 + r0c) * KDIM) + cc * 16;
    const char* Bg = (const char*)(g_B + (size_t)(n0 + r0c) * KDIM) + cc * 16;
    const size_t grow32 = (size_t)32 * KDIM * 2;   // 32 GMEM rows

    // +32 rows = +4096 B (bit 12) commutes past the SW128 swizzle field
    uint32_t stA0 = swz((uint32_t)(r0c * 128 + cc * 16));
    uint32_t stB0 = (uint32_t)A_ST_BYTES + stA0;

    // ---- ldmatrix base offsets; per-ks address = pre ^ (ks*32) ----
    int mid = lane >> 3;          // matrix id 0..3
    int lr  = lane & 7;
    uint32_t preA[2], preB[4];
    #pragma unroll
    for (int mt = 0; mt < 2; mt++) {
        int row = wm * 32 + mt * 16 + (mid & 1) * 8 + lr;
        int sk  = (mid >> 1) * 16;
        preA[mt] = swz((uint32_t)(row * 128 + sk));
    }
    #pragma unroll
    for (int nt = 0; nt < 4; nt++) {
        int row = wn * 64 + nt * 16 + (mid >> 1) * 8 + lr;
        int sk  = (mid & 1) * 16;
        preB[nt] = (uint32_t)A_ST_BYTES + swz((uint32_t)(row * 128 + sk));
    }

    float acc[2][8][4];
    #pragma unroll
    for (int mt = 0; mt < 2; mt++)
        #pragma unroll
        for (int nn = 0; nn < 8; nn++)
            #pragma unroll
            for (int j = 0; j < 4; j++) acc[mt][nn][j] = 0.0f;

    // ---- prologue: fill stages 0,1 with k-tiles 0,1 ----
    #pragma unroll
    for (int p = 0; p < STAGES - 1; p++) {
        uint32_t st = stg + p * STAGE_BYTES;
        size_t ko = (size_t)p * 128;   // BK*2 bytes
        #pragma unroll
        for (int i = 0; i < 4; i++) {
            CP16(st + stA0 + 4096 * i, Ag + grow32 * i + ko);
            CP16(st + stB0 + 4096 * i, Bg + grow32 * i + ko);
        }
        CP_MB_ARRIVE(sb + 8 * p);
    }

    // ---- main loop ----
    int s = 0, sf = STAGES - 1;
    uint32_t phF = 0;             // per-stage phase bits (full only)
    for (int kt = 0; kt < KTILES; kt++) {
        // data ready for stage s?
        MB_WAIT(sb + 8 * s, (phF >> s) & 1);
        phF ^= 1u << s;
        uint32_t st = stg + s * STAGE_BYTES;

        // issue ks=0 fragment loads first (latency cover for the fill below)
        uint32_t a0[2][4], b0[4][4];
        LDSM4(a0[0], st + preA[0]);
        LDSM4(a0[1], st + preA[1]);
        #pragma unroll
        for (int nt = 0; nt < 4; nt++)
            LDSM4(b0[nt], st + preB[nt]);

        // fill stage sf with k-tile kt+2.  sf is the stage consumed at iter
        // kt-1; the __syncthreads at the end of kt-1 proved it free.
        int kn = kt + STAGES - 1;
        if (kn < KTILES) {
            uint32_t stf = stg + sf * STAGE_BYTES;
            size_t ko = (size_t)kn * 128;
            #pragma unroll
            for (int i = 0; i < 4; i++) {
                CP16(stf + stA0 + 4096 * i, Ag + grow32 * i + ko);
                CP16(stf + stB0 + 4096 * i, Bg + grow32 * i + ko);
            }
            CP_MB_ARRIVE(sb + 8 * sf);
        }

        // ks = 0 compute (fragments already in flight)
        #pragma unroll
        for (int mt = 0; mt < 2; mt++)
            #pragma unroll
            for (int nn = 0; nn < 8; nn++)
                mma16816(acc[mt][nn], a0[mt], &b0[nn >> 1][(nn & 1) * 2]);

        // ks = 1..3
        #pragma unroll
        for (int ks = 1; ks < 4; ks++) {
            uint32_t kx = (uint32_t)(ks * 32);
            uint32_t a[2][4], b[4][4];
            LDSM4(a[0], st + (preA[0] ^ kx));
            LDSM4(a[1], st + (preA[1] ^ kx));
            #pragma unroll
            for (int nt = 0; nt < 4; nt++)
                LDSM4(b[nt], st + (preB[nt] ^ kx));
            #pragma unroll
            for (int mt = 0; mt < 2; mt++)
                #pragma unroll
                for (int nn = 0; nn < 8; nn++)
                    mma16816(acc[mt][nn], a[mt], &b[nn >> 1][(nn & 1) * 2]);
        }

        // all reads of stage s consumed by the mma above -> barrier frees it
        __syncthreads();

        s  = (s  + 1 == STAGES) ? 0 : s + 1;
        sf = (sf + 1 == STAGES) ? 0 : sf + 1;
    }

    // ---- epilogue: fused dequant + bias, straight from registers ----
    float s0 = gscale[0];
    #pragma unroll
    for (int mt = 0; mt < 2; mt++) {
        int r0 = m0 + wm * 32 + mt * 16 + (lane >> 2);
        float sx0 = scale_x[r0] * s0;
        float sx1 = scale_x[r0 + 8] * s0;
        float* o0 = out + (size_t)r0 * ODIM;
        float* o1 = out + (size_t)(r0 + 8) * ODIM;
        #pragma unroll
        for (int nn = 0; nn < 8; nn++) {
            int c = n0 + wn * 64 + nn * 8 + (lane & 3) * 2;
            float w0 = scale_w[c], w1 = scale_w[c + 1];
            float b0 = bias[c],    b1 = bias[c + 1];
            float2 v0, v1;
            v0.x = acc[mt][nn][0] * sx0 * w0 + b0;
            v0.y = acc[mt][nn][1] * sx0 * w1 + b1;
            v1.x = acc[mt][nn][2] * sx1 * w0 + b0;
            v1.y = acc[mt][nn][3] * sx1 * w1 + b1;
            *(float2*)(o0 + c) = v0;
            *(float2*)(o1 + c) = v1;
        }
    }
}

// ---------------- launch ----------------
extern "C" void kernel_launch(void* const* d_in, const int* in_sizes, int n_in,
                              void* d_out, int out_size) {
    const float* qx      = (const float*)d_in[0];   // (T, K)
    const float* W       = (const float*)d_in[1];   // (O, K)
    const float* scale_x = (const float*)d_in[2];   // (T, 1)
    const float* scale_w = (const float*)d_in[3];   // (O,)
    const float* scale   = (const float*)d_in[4];   // (1,)
    const float* bias    = (const float*)d_in[5];   // (O,)
    float* out = (float*)d_out;                     // (T, O) fp32

    void* pA = nullptr; void* pB = nullptr;
    cudaGetSymbolAddress(&pA, g_A);
    cudaGetSymbolAddress(&pB, g_B);

    size_t nA8 = (size_t)T_TOK * KDIM / 8;
    size_t nB8 = (size_t)ODIM * KDIM / 8;
    cvt_fused_kernel<<<2960, 256>>>(qx, W, (__half*)pA, (__half*)pB,
                                    nA8, nA8 + nB8);

    cudaFuncSetAttribute(qgemm_kernel,
                         cudaFuncAttributeMaxDynamicSharedMemorySize, SMEM_TOTAL);
    dim3 grid(ODIM / BN, T_TOK / BM);  // (32, 64)
    qgemm_kernel<<<grid, 256, SMEM_TOTAL>>>(scale_x, scale_w, scale, bias, out);
}

// round 17
// speedup vs baseline: 1.1230x; 1.1230x over previous
#include <cuda_runtime.h>
#include <cuda_fp16.h>
#include <cstdint>
#include <cstddef>

// Problem dims (fixed by the dataset)
#define T_TOK 8192
#define KDIM  4096
#define ODIM  4096

// GEMM tiling
#define BM 128
#define BN 128
#define BK 64                 // 64 fp16 = 128 B per smem row (full SW128)
#define STAGES 3
#define KTILES (KDIM / BK)    // 64

#define A_ST_BYTES (BM * 128) // 16384
#define B_ST_BYTES (BN * 128) // 16384
#define STAGE_BYTES (A_ST_BYTES + B_ST_BYTES)   // 32768
#define SMEM_TOTAL (1024 + STAGES * STAGE_BYTES) // 99328 (2 CTAs fit in 228K)

// fp16 scratch for converted operands (allocation-free: device globals)
__device__ __half g_A[(size_t)T_TOK * KDIM];   // 64 MB
__device__ __half g_B[(size_t)ODIM * KDIM];    // 32 MB

// ---------------- helpers ----------------
__device__ __forceinline__ uint32_t smem_u32(const void* p) {
    uint32_t a;
    asm("{ .reg .u64 t; cvta.to.shared.u64 t, %1; cvt.u32.u64 %0, t; }"
        : "=r"(a) : "l"(p));
    return a;
}

__device__ __forceinline__ uint32_t h2_bits(__half2 h) {
    uint32_t u;
    *reinterpret_cast<__half2*>(&u) = h;
    return u;
}

// SW128 swizzle for 128B rows: XOR 16B-chunk bits [6:4] with row bits [9:7]
__device__ __forceinline__ uint32_t swz(uint32_t off) {
    return off ^ ((off >> 3) & 0x70);
}

#define CP16(dst, src) \
    asm volatile("cp.async.cg.shared.global [%0], [%1], 16;" \
                 :: "r"(dst), "l"(src) : "memory")

// one arrival on [mbar] when ALL of this thread's prior cp.asyncs complete
#define CP_MB_ARRIVE(mbar) \
    asm volatile("cp.async.mbarrier.arrive.noinc.shared::cta.b64 [%0];" \
                 :: "r"(mbar) : "memory")

#define MB_INIT(a, c) \
    asm volatile("mbarrier.init.shared.b64 [%0], %1;" :: "r"(a), "r"(c) : "memory")

#define MB_ARRIVE(a) \
    asm volatile("mbarrier.arrive.shared.b64 _, [%0];" :: "r"(a) : "memory")

#define MB_WAIT(addr, ph) do {                                                     \
    uint32_t _done = 0;                                                            \
    while (!_done) {                                                               \
        asm volatile("{\n\t.reg .pred p;\n\t"                                      \
            "mbarrier.try_wait.parity.acquire.cta.shared::cta.b64 p, [%1], %2, 0x989680;\n\t" \
            "selp.b32 %0, 1, 0, p;\n\t}"                                           \
            : "=r"(_done) : "r"((uint32_t)(addr)), "r"((uint32_t)(ph)) : "memory"); \
    }                                                                              \
} while (0)

#define LDSM4(r, a)                                                             \
    asm volatile("ldmatrix.sync.aligned.m8n8.x4.shared.b16 {%0,%1,%2,%3}, [%4];" \
        : "=r"((r)[0]), "=r"((r)[1]), "=r"((r)[2]), "=r"((r)[3]) : "r"(a))

__device__ __forceinline__ void mma16816(float* d, const uint32_t* a,
                                         const uint32_t* b) {
    asm volatile(
        "mma.sync.aligned.m16n8k16.row.col.f32.f16.f16.f32 "
        "{%0,%1,%2,%3}, {%4,%5,%6,%7}, {%8,%9}, {%0,%1,%2,%3};"
        : "+f"(d[0]), "+f"(d[1]), "+f"(d[2]), "+f"(d[3])
        : "r"(a[0]), "r"(a[1]), "r"(a[2]), "r"(a[3]), "r"(b[0]), "r"(b[1]));
}

// ---------------- fused convert fp32 -> fp16 (lossless: exact ints <= 448) ----
__global__ void cvt_fused_kernel(const float* __restrict__ qx,
                                 const float* __restrict__ W,
                                 __half* __restrict__ dA, __half* __restrict__ dB,
                                 size_t nA8, size_t nTot8) {
    size_t i = (size_t)blockIdx.x * blockDim.x + threadIdx.x;
    size_t stride = (size_t)gridDim.x * blockDim.x;
    for (; i < nTot8; i += stride) {
        const float4* s4;
        uint4* d4;
        if (i < nA8) {
            s4 = (const float4*)qx + 2 * i;
            d4 = (uint4*)dA + i;
        } else {
            size_t j = i - nA8;
            s4 = (const float4*)W + 2 * j;
            d4 = (uint4*)dB + j;
        }
        float4 v0 = s4[0];
        float4 v1 = s4[1];
        uint4 o;
        o.x = h2_bits(__floats2half2_rn(v0.x, v0.y));
        o.y = h2_bits(__floats2half2_rn(v0.z, v0.w));
        o.z = h2_bits(__floats2half2_rn(v1.x, v1.y));
        o.w = h2_bits(__floats2half2_rn(v1.z, v1.w));
        *d4 = o;
    }
}

// ---------------- pipelined HMMA GEMM + fused dequant epilogue ----------------
// Software-pipelined across stages: the full-wait for stage s+1 executes AFTER
// the ks=3 mma burst of stage s is issued, hidden under the burst's tensor
// drain.  Iteration heads start with fragments already in registers.
// mbarriers as R12: full[s]=256 cp.async arrivals, empty[s]=256 thread arrives.
__global__ void __launch_bounds__(256, 2)
qgemm_kernel(const float* __restrict__ scale_x, const float* __restrict__ scale_w,
             const float* __restrict__ gscale,  const float* __restrict__ bias,
             float* __restrict__ out) {
    extern __shared__ char smem[];
    uint32_t sb = smem_u32(smem);
    int tid = threadIdx.x;
    int lane = tid & 31;
    int wid = tid >> 5;          // 0..7
    int wm = wid >> 1;           // 0..3   (M dim, 32 rows each)
    int wn = wid & 1;            // 0..1   (N dim, 64 cols each)
    int m0 = blockIdx.y * BM;
    int n0 = blockIdx.x * BN;

    // mbarriers: full[s] at sb+8s, empty[s] at sb+24+8s; stages at sb+1024
    if (tid == 0) {
        #pragma unroll
        for (int s3 = 0; s3 < STAGES; s3++) {
            MB_INIT(sb + 8 * s3, 256);
            MB_INIT(sb + 24 + 8 * s3, 256);
        }
    }
    __syncthreads();
    uint32_t stg = sb + 1024;

    // ---- cp.async thread mapping: 8 x 16B chunks per thread per stage ----
    int r0c = tid >> 3, cc = tid & 7;    // base row 0..31 / chunk col

    const char* Ag = (const char*)(g_A + (size_t)(m0 + r0c) * KDIM) + cc * 16;
    const char* Bg = (const char*)(g_B + (size_t)(n0 + r0c) * KDIM) + cc * 16;
    const size_t grow32 = (size_t)32 * KDIM * 2;   // 32 GMEM rows

    // +32 rows = +4096 B (bit 12) commutes past the SW128 swizzle field
    uint32_t stA0 = swz((uint32_t)(r0c * 128 + cc * 16));
    uint32_t stB0 = (uint32_t)A_ST_BYTES + stA0;

    // ---- ldmatrix base offsets; per-ks address = pre ^ (ks*32) ----
    int mid = lane >> 3;          // matrix id 0..3
    int lr  = lane & 7;
    uint32_t preA[2], preB[4];
    #pragma unroll
    for (int mt = 0; mt < 2; mt++) {
        int row = wm * 32 + mt * 16 + (mid & 1) * 8 + lr;
        int sk  = (mid >> 1) * 16;
        preA[mt] = swz((uint32_t)(row * 128 + sk));
    }
    #pragma unroll
    for (int nt = 0; nt < 4; nt++) {
        int row = wn * 64 + nt * 16 + (mid >> 1) * 8 + lr;
        int sk  = (mid & 1) * 16;
        preB[nt] = (uint32_t)A_ST_BYTES + swz((uint32_t)(row * 128 + sk));
    }

    float acc[2][8][4];
    #pragma unroll
    for (int mt = 0; mt < 2; mt++)
        #pragma unroll
        for (int nn = 0; nn < 8; nn++)
            #pragma unroll
            for (int j = 0; j < 4; j++) acc[mt][nn][j] = 0.0f;

    // ---- prologue: fill stages 0,1 with k-tiles 0,1 ----
    #pragma unroll
    for (int p = 0; p < STAGES - 1; p++) {
        uint32_t st = stg + p * STAGE_BYTES;
        size_t ko = (size_t)p * 128;   // BK*2 bytes
        #pragma unroll
        for (int i = 0; i < 4; i++) {
            CP16(st + stA0 + 4096 * i, Ag + grow32 * i + ko);
            CP16(st + stB0 + 4096 * i, Bg + grow32 * i + ko);
        }
        CP_MB_ARRIVE(sb + 8 * p);
    }

    // persistent fragment set (loaded at tail of previous iteration)
    uint32_t af[2][4], bf[4][4];

    // software-pipeline prologue: wait stage 0, load ks=0 fragments
    MB_WAIT(sb + 8 * 0, 0);
    {
        uint32_t st = stg;
        LDSM4(af[0], st + preA[0]);
        LDSM4(af[1], st + preA[1]);
        #pragma unroll
        for (int nt = 0; nt < 4; nt++)
            LDSM4(bf[nt], st + preB[nt]);
    }

    // ---- main loop ----
    int s = 0, sf = STAGES - 1;
    uint32_t phF = 1;             // stage0 already waited (phase flipped)
    uint32_t phE = 0;
    #pragma unroll 1
    for (int kt = 0; kt < KTILES; kt++) {
        uint32_t st = stg + s * STAGE_BYTES;

        // fill stage sf with k-tile kt+2 (stage consumed at iter kt-1)
        int kn = kt + STAGES - 1;
        if (kn < KTILES) {
            if (kt > 0) {   // first fill of stage 2 (kt==0) has no prior readers
                MB_WAIT(sb + 24 + 8 * sf, (phE >> sf) & 1);
                phE ^= 1u << sf;
            }
            uint32_t stf = stg + sf * STAGE_BYTES;
            size_t ko = (size_t)kn * 128;
            #pragma unroll
            for (int i = 0; i < 4; i++) {
                CP16(stf + stA0 + 4096 * i, Ag + grow32 * i + ko);
                CP16(stf + stB0 + 4096 * i, Bg + grow32 * i + ko);
            }
            CP_MB_ARRIVE(sb + 8 * sf);
        }

        // ks = 0..2: mma burst with resident frags, then load ks+1 frags
        #pragma unroll
        for (int ks = 0; ks < 3; ks++) {
            #pragma unroll
            for (int mt = 0; mt < 2; mt++)
                #pragma unroll
                for (int nn = 0; nn < 8; nn++)
                    mma16816(acc[mt][nn], af[mt], &bf[nn >> 1][(nn & 1) * 2]);
            uint32_t kx = (uint32_t)((ks + 1) * 32);
            LDSM4(af[0], st + (preA[0] ^ kx));    // WAR: frags consumed at issue
            LDSM4(af[1], st + (preA[1] ^ kx));
            #pragma unroll
            for (int nt = 0; nt < 4; nt++)
                LDSM4(bf[nt], st + (preB[nt] ^ kx));
        }

        // ks = 3: final burst, then (hidden under its drain) release stage,
        // wait next stage, and load its ks=0 fragments
        #pragma unroll
        for (int mt = 0; mt < 2; mt++)
            #pragma unroll
            for (int nn = 0; nn < 8; nn++)
                mma16816(acc[mt][nn], af[mt], &bf[nn >> 1][(nn & 1) * 2]);
        MB_ARRIVE(sb + 24 + 8 * s);               // done reading stage s

        if (kt < KTILES - 1) {
            int s2 = (s + 1 == STAGES) ? 0 : s + 1;
            MB_WAIT(sb + 8 * s2, (phF >> s2) & 1);
            phF ^= 1u << s2;
            uint32_t st2 = stg + s2 * STAGE_BYTES;
            LDSM4(af[0], st2 + preA[0]);
            LDSM4(af[1], st2 + preA[1]);
            #pragma unroll
            for (int nt = 0; nt < 4; nt++)
                LDSM4(bf[nt], st2 + preB[nt]);
        }

        s  = (s  + 1 == STAGES) ? 0 : s + 1;
        sf = (sf + 1 == STAGES) ? 0 : sf + 1;
    }

    // ---- epilogue: fused dequant + bias, straight from registers ----
    float s0 = gscale[0];
    #pragma unroll
    for (int mt = 0; mt < 2; mt++) {
        int r0 = m0 + wm * 32 + mt * 16 + (lane >> 2);
        float sx0 = scale_x[r0] * s0;
        float sx1 = scale_x[r0 + 8] * s0;
        float* o0 = out + (size_t)r0 * ODIM;
        float* o1 = out + (size_t)(r0 + 8) * ODIM;
        #pragma unroll
        for (int nn = 0; nn < 8; nn++) {
            int c = n0 + wn * 64 + nn * 8 + (lane & 3) * 2;
            float w0 = scale_w[c], w1 = scale_w[c + 1];
            float b0 = bias[c],    b1 = bias[c + 1];
            float2 v0, v1;
            v0.x = acc[mt][nn][0] * sx0 * w0 + b0;
            v0.y = acc[mt][nn][1] * sx0 * w1 + b1;
            v1.x = acc[mt][nn][2] * sx1 * w0 + b0;
            v1.y = acc[mt][nn][3] * sx1 * w1 + b1;
            *(float2*)(o0 + c) = v0;
            *(float2*)(o1 + c) = v1;
        }
    }
}

// ---------------- launch ----------------
extern "C" void kernel_launch(void* const* d_in, const int* in_sizes, int n_in,
                              void* d_out, int out_size) {
    const float* qx      = (const float*)d_in[0];   // (T, K)
    const float* W       = (const float*)d_in[1];   // (O, K)
    const float* scale_x = (const float*)d_in[2];   // (T, 1)
    const float* scale_w = (const float*)d_in[3];   // (O,)
    const float* scale   = (const float*)d_in[4];   // (1,)
    const float* bias    = (const float*)d_in[5];   // (O,)
    float* out = (float*)d_out;                     // (T, O) fp32

    void* pA = nullptr; void* pB = nullptr;
    cudaGetSymbolAddress(&pA, g_A);
    cudaGetSymbolAddress(&pB, g_B);

    size_t nA8 = (size_t)T_TOK * KDIM / 8;
    size_t nB8 = (size_t)ODIM * KDIM / 8;
    cvt_fused_kernel<<<2960, 256>>>(qx, W, (__half*)pA, (__half*)pB,
                                    nA8, nA8 + nB8);

    cudaFuncSetAttribute(qgemm_kernel,
                         cudaFuncAttributeMaxDynamicSharedMemorySize, SMEM_TOTAL);
    dim3 grid(ODIM / BN, T_TOK / BM);  // (32, 64)
    qgemm_kernel<<<grid, 256, SMEM_TOTAL>>>(scale_x, scale_w, scale, bias, out);
}